// round 10
// baseline (speedup 1.0000x reference)
#include <cuda_runtime.h>
#include <cuda_bf16.h>

// Net: x[B,2] -> fc1(9) -> ELU -> 19 x (fc 9x9 -> ELU) -> fc(2) -> log_softmax
// fp32 packed f32x2 math, NP=2 row-pairs/thread, IT=2 pair-sets per thread.
// Wide LDS.128 weight loads + 2-output-row x 2-pair interleave (4 chains).
// Scale domain: activations a = log2(e)*elu(z); mid W unchanged, biases *L2E,
// W1,b1 *L2E, W21 *1/L2E.

#define THREADS 128
#define NP 2
#define IT 2

static const int B_ROWS      = 2097152;
static const int NPAIR       = B_ROWS / 2;              // 1,048,576
static const int TOT_THREADS = NPAIR / NP;              // 524,288
static const int NBLOCK      = TOT_THREADS / THREADS / IT;   // 2048

typedef unsigned long long u64;

#define L2E  1.4426950408889634f
#define IL2E 0.6931471805599453f
#define LN2  0.6931471805599453f

// shared layout (u64 units). Mid rows: [w0..w8, bias] = 10 u64 = 5 x LDS.128.
#define OFF_MW   0                   // 19*90 ; layer l row j at l*90 + j*10
#define OFF_W1   1710                // 9 rows * 4 : [w0, w1, bias, pad]   (scaled L2E)
#define OFF_W21  1746                // 2 rows * 10: [w0..w8, bias]        (W scaled 1/L2E)
#define SW_TOT   1766

__device__ __forceinline__ u64 pk2(float lo, float hi) {
    u64 r; asm("mov.b64 %0,{%1,%2};" : "=l"(r) : "f"(lo), "f"(hi)); return r;
}
__device__ __forceinline__ void upk2(float& lo, float& hi, u64 v) {
    asm("mov.b64 {%0,%1},%2;" : "=f"(lo), "=f"(hi) : "l"(v));
}
__device__ __forceinline__ u64 ffma2(u64 a, u64 b, u64 c) {
    u64 d; asm("fma.rn.f32x2 %0,%1,%2,%3;" : "=l"(d) : "l"(a), "l"(b), "l"(c)); return d;
}
__device__ __forceinline__ float ex2(float x) {
    float r; asm("ex2.approx.ftz.f32 %0, %1;" : "=f"(r) : "f"(x)); return r;
}
__device__ __forceinline__ float lg2(float x) {
    float r; asm("lg2.approx.ftz.f32 %0, %1;" : "=f"(r) : "f"(x)); return r;
}

// scale-domain packed ELU (5 issues per u64):
//   e = {EX2(-|lo|), EX2(-|hi|)};  r = ffma2(e,{L2E},{-L2E});  out = max(a,r) per half
// a>0: r<0 -> exact a.  a<=0: L2E*(e^z-1).  EX2 arg <= 0, no overflow.
__device__ __forceinline__ u64 elu2s(u64 v) {
    float lo, hi; upk2(lo, hi, v);
    float elo = ex2(-fabsf(lo));
    float ehi = ex2(-fabsf(hi));
    u64 r = ffma2(pk2(elo, ehi), pk2(L2E, L2E), pk2(-L2E, -L2E));
    float rlo, rhi; upk2(rlo, rhi, r);
    return pk2(fmaxf(lo, rlo), fmaxf(hi, rhi));
}

// log_softmax over 2 logits, MUFU-based:
// lse = max + ln2 * lg2(1 + 2^(-|d|*log2e))
__device__ __forceinline__ void lsm2(float l0, float l1, float& o0, float& o1) {
    float m   = fmaxf(l0, l1);
    float t   = ex2(-fabsf(l0 - l1) * L2E);
    float lse = fmaf(lg2(1.0f + t), LN2, m);
    o0 = l0 - lse;
    o1 = l1 - lse;
}

// one 9x9 mid layer + ELU, 2 output rows x 2 pairs = 4 independent chains,
// wide LDS.128 weight loads.
__device__ __forceinline__ void mid_layer(const u64* __restrict__ wl,
                                          u64 (&in)[NP][9], u64 (&out)[NP][9])
{
#pragma unroll
    for (int jj = 0; jj < 4; jj++) {
        const u64* wr0 = wl + (2 * jj)     * 10;
        const u64* wr1 = wl + (2 * jj + 1) * 10;

        ulonglong2 a8 = *reinterpret_cast<const ulonglong2*>(wr0 + 8);
        ulonglong2 b8 = *reinterpret_cast<const ulonglong2*>(wr1 + 8);
        u64 p00 = ffma2(a8.x, in[0][8], a8.y);
        u64 p01 = ffma2(a8.x, in[1][8], a8.y);
        u64 p10 = ffma2(b8.x, in[0][8], b8.y);
        u64 p11 = ffma2(b8.x, in[1][8], b8.y);

#pragma unroll
        for (int k = 0; k < 4; k++) {
            ulonglong2 wa = *reinterpret_cast<const ulonglong2*>(wr0 + 2 * k);
            ulonglong2 wb = *reinterpret_cast<const ulonglong2*>(wr1 + 2 * k);
            u64 i0 = in[0][2 * k],     i1 = in[1][2 * k];
            u64 j0 = in[0][2 * k + 1], j1 = in[1][2 * k + 1];
            p00 = ffma2(wa.x, i0, p00);
            p01 = ffma2(wa.x, i1, p01);
            p10 = ffma2(wb.x, i0, p10);
            p11 = ffma2(wb.x, i1, p11);
            p00 = ffma2(wa.y, j0, p00);
            p01 = ffma2(wa.y, j1, p01);
            p10 = ffma2(wb.y, j0, p10);
            p11 = ffma2(wb.y, j1, p11);
        }

        out[0][2 * jj]     = elu2s(p00);
        out[1][2 * jj]     = elu2s(p01);
        out[0][2 * jj + 1] = elu2s(p10);
        out[1][2 * jj + 1] = elu2s(p11);
    }

    // row 8 solo (2 chains)
    {
        const u64* wr = wl + 8 * 10;
        ulonglong2 w8b = *reinterpret_cast<const ulonglong2*>(wr + 8);
        u64 p0 = ffma2(w8b.x, in[0][8], w8b.y);
        u64 p1 = ffma2(w8b.x, in[1][8], w8b.y);
#pragma unroll
        for (int k = 0; k < 4; k++) {
            ulonglong2 wa = *reinterpret_cast<const ulonglong2*>(wr + 2 * k);
            p0 = ffma2(wa.x, in[0][2 * k], p0);
            p1 = ffma2(wa.x, in[1][2 * k], p1);
            p0 = ffma2(wa.y, in[0][2 * k + 1], p0);
            p1 = ffma2(wa.y, in[1][2 * k + 1], p1);
        }
        out[0][8] = elu2s(p0);
        out[1][8] = elu2s(p1);
    }
}

__global__ void __launch_bounds__(THREADS, 4)
mlp_kernel(const float* __restrict__ x,
           const float* __restrict__ W1,  const float* __restrict__ b1,
           const float* __restrict__ Wm,  const float* __restrict__ bm,
           const float* __restrict__ W21, const float* __restrict__ b21,
           float* __restrict__ out)
{
    __shared__ __align__(16) u64 sw[SW_TOT];
    const int t = threadIdx.x;
    const int gtid0 = blockIdx.x * (THREADS * IT) + t;

    // All IT*NP input loads up front: DRAM latency overlaps weight staging,
    // and iteration 2's inputs are already resident when it starts.
    int    pidx[IT][NP];
    float4 xin[IT][NP];
#pragma unroll
    for (int it = 0; it < IT; it++)
#pragma unroll
        for (int p = 0; p < NP; p++) {
            pidx[it][p] = gtid0 + it * THREADS + p * TOT_THREADS;   // coalesced
            xin[it][p]  = reinterpret_cast<const float4*>(x)[pidx[it][p]];
        }

    // Stage weights into shared, duplicated {w,w}, scaled per plan.
    for (int i = t; i < 19 * 81; i += THREADS) {
        int l = i / 81, r = i % 81;
        int j = r / 9,  k = r % 9;
        float v = Wm[i];
        sw[OFF_MW + l * 90 + j * 10 + k] = pk2(v, v);
    }
    for (int i = t; i < 19 * 9; i += THREADS) {
        int l = i / 9, j = i % 9;
        float v = bm[i] * L2E;
        sw[OFF_MW + l * 90 + j * 10 + 9] = pk2(v, v);
    }
    if (t < 9) {
        float w0 = W1[t * 2 + 0] * L2E;
        float w1 = W1[t * 2 + 1] * L2E;
        float bb = b1[t] * L2E;
        sw[OFF_W1 + t * 4 + 0] = pk2(w0, w0);
        sw[OFF_W1 + t * 4 + 1] = pk2(w1, w1);
        sw[OFF_W1 + t * 4 + 2] = pk2(bb, bb);
        sw[OFF_W1 + t * 4 + 3] = 0ull;
    }
    if (t >= 32 && t < 50) {
        int i = t - 32;
        int o = i / 9, k = i % 9;
        float v = W21[i] * IL2E;
        sw[OFF_W21 + o * 10 + k] = pk2(v, v);
    }
    if (t >= 64 && t < 66) {
        int o = t - 64;
        sw[OFF_W21 + o * 10 + 9] = pk2(b21[o], b21[o]);
    }
    __syncthreads();

#pragma unroll 1
    for (int it = 0; it < IT; it++) {
        u64 h[NP][9], g[NP][9];

        // ---- fc1 (pre-scaled L2E) + ELU ----
#pragma unroll
        for (int p = 0; p < NP; p++) {
            u64 x0 = pk2(xin[it][p].x, xin[it][p].z);
            u64 x1 = pk2(xin[it][p].y, xin[it][p].w);
#pragma unroll
            for (int j = 0; j < 9; j++) {
                u64 acc = ffma2(sw[OFF_W1 + j * 4 + 0], x0, sw[OFF_W1 + j * 4 + 2]);
                acc     = ffma2(sw[OFF_W1 + j * 4 + 1], x1, acc);
                h[p][j] = elu2s(acc);
            }
        }

        // ---- 19 mid layers: 9 x (h->g, g->h) + final h->g ----
#pragma unroll 1
        for (int l = 0; l < 9; l++) {
            mid_layer(&sw[OFF_MW + (2 * l)     * 90], h, g);
            mid_layer(&sw[OFF_MW + (2 * l + 1) * 90], g, h);
        }
        mid_layer(&sw[OFF_MW + 18 * 90], h, g);

        // ---- output layer (W21 pre-scaled 1/L2E) + log_softmax ----
        // 4 chains: 2 outputs x 2 pairs, wide weight loads.
        {
            const u64* wr0 = &sw[OFF_W21 + 0];
            const u64* wr1 = &sw[OFF_W21 + 10];
            ulonglong2 a8 = *reinterpret_cast<const ulonglong2*>(wr0 + 8);
            ulonglong2 b8 = *reinterpret_cast<const ulonglong2*>(wr1 + 8);
            u64 p00 = ffma2(a8.x, g[0][8], a8.y);
            u64 p01 = ffma2(a8.x, g[1][8], a8.y);
            u64 p10 = ffma2(b8.x, g[0][8], b8.y);
            u64 p11 = ffma2(b8.x, g[1][8], b8.y);
#pragma unroll
            for (int k = 0; k < 4; k++) {
                ulonglong2 wa = *reinterpret_cast<const ulonglong2*>(wr0 + 2 * k);
                ulonglong2 wb = *reinterpret_cast<const ulonglong2*>(wr1 + 2 * k);
                p00 = ffma2(wa.x, g[0][2 * k], p00);
                p01 = ffma2(wa.x, g[1][2 * k], p01);
                p10 = ffma2(wb.x, g[0][2 * k], p10);
                p11 = ffma2(wb.x, g[1][2 * k], p11);
                p00 = ffma2(wa.y, g[0][2 * k + 1], p00);
                p01 = ffma2(wa.y, g[1][2 * k + 1], p01);
                p10 = ffma2(wb.y, g[0][2 * k + 1], p10);
                p11 = ffma2(wb.y, g[1][2 * k + 1], p11);
            }

            float l0A, l0B, l1A, l1B;
            float4 o;

            upk2(l0A, l0B, p00);           // pair 0: logit0 rows A,B
            upk2(l1A, l1B, p10);           // pair 0: logit1 rows A,B
            lsm2(l0A, l1A, o.x, o.y);
            lsm2(l0B, l1B, o.z, o.w);
            reinterpret_cast<float4*>(out)[pidx[it][0]] = o;

            upk2(l0A, l0B, p01);           // pair 1
            upk2(l1A, l1B, p11);
            lsm2(l0A, l1A, o.x, o.y);
            lsm2(l0B, l1B, o.z, o.w);
            reinterpret_cast<float4*>(out)[pidx[it][1]] = o;
        }
    }
}

extern "C" void kernel_launch(void* const* d_in, const int* in_sizes, int n_in,
                              void* d_out, int out_size)
{
    const float* x   = (const float*)d_in[0];
    const float* W1  = (const float*)d_in[1];
    const float* b1  = (const float*)d_in[2];
    const float* Wm  = (const float*)d_in[3];
    const float* bm  = (const float*)d_in[4];
    const float* W21 = (const float*)d_in[5];
    const float* b21 = (const float*)d_in[6];
    float*       out = (float*)d_out;

    mlp_kernel<<<NBLOCK, THREADS>>>(x, W1, b1, Wm, bm, W21, b21, out);
}

// round 11
// speedup vs baseline: 1.2579x; 1.2579x over previous
#include <cuda_runtime.h>
#include <cuda_bf16.h>

// Net: x[B,2] -> fc1(9) -> ELU -> 19 x (fc 9x9 -> ELU) -> fc(2) -> log_softmax
// fp32 packed f32x2 math, NP=2 row-pairs/thread (4 batch rows) to amortize LDS.
// R2-champion structure: wide LDS.128 weight loads, separate bias array,
// 2 interleaved accumulator chains, natural register allocation.
// Scale-domain ELU: activations a = log2(e)*elu(z); mid W unchanged,
// biases *= L2E, W1,b1 *= L2E, W21 *= 1/L2E.

#define THREADS 128
#define NP 2

static const int B_ROWS      = 2097152;
static const int NPAIR       = B_ROWS / 2;              // 1,048,576
static const int TOT_THREADS = NPAIR / NP;              // 524,288
static const int NBLOCK      = TOT_THREADS / THREADS;   // 4096

typedef unsigned long long u64;

#define L2E  1.4426950408889634f
#define IL2E 0.6931471805599453f
#define LN2  0.6931471805599453f

// shared layout in u64 units (rows padded to 10 for LDS.128 alignment)
#define OFF_MW   0                   // 19 * 9 * 10 = 1710 ; w[l][j][k] at l*90 + j*10 + k
#define OFF_MB   1710                // 19 * 10 = 190      ; b[l][j] at l*10 + j (scaled L2E)
#define OFF_W1   1900                // 18 : W1[j][k] at j*2+k (scaled L2E)
#define OFF_B1   1918                // 9  (scaled L2E)
#define OFF_W21  1928                // 18 : W21[o][k] at o*9+k (scaled 1/L2E)
#define OFF_B21  1946                // 2
#define SW_TOT   1948

__device__ __forceinline__ u64 pk2(float lo, float hi) {
    u64 r; asm("mov.b64 %0,{%1,%2};" : "=l"(r) : "f"(lo), "f"(hi)); return r;
}
__device__ __forceinline__ void upk2(float& lo, float& hi, u64 v) {
    asm("mov.b64 {%0,%1},%2;" : "=f"(lo), "=f"(hi) : "l"(v));
}
__device__ __forceinline__ u64 ffma2(u64 a, u64 b, u64 c) {
    u64 d; asm("fma.rn.f32x2 %0,%1,%2,%3;" : "=l"(d) : "l"(a), "l"(b), "l"(c)); return d;
}
__device__ __forceinline__ float ex2(float x) {
    float r; asm("ex2.approx.ftz.f32 %0, %1;" : "=f"(r) : "f"(x)); return r;
}
__device__ __forceinline__ float lg2(float x) {
    float r; asm("lg2.approx.ftz.f32 %0, %1;" : "=f"(r) : "f"(x)); return r;
}

// scale-domain ELU, scalar form (3 issues per half, no pack/unpack MOVs):
//   r = fmaf(EX2(-|a|), L2E, -L2E);  out = max(a, r)
// a>0: r<0 -> exact a.  a<=0: L2E*(e^z-1).  EX2 arg <= 0, no overflow.
__device__ __forceinline__ u64 elu2s(u64 v) {
    float lo, hi; upk2(lo, hi, v);
    float rlo = fmaf(ex2(-fabsf(lo)), L2E, -L2E);
    float rhi = fmaf(ex2(-fabsf(hi)), L2E, -L2E);
    return pk2(fmaxf(lo, rlo), fmaxf(hi, rhi));
}

// log_softmax over 2 logits, MUFU-based:
// lse = max + ln2 * lg2(1 + 2^(-|d|*log2e))
__device__ __forceinline__ void lsm2(float l0, float l1, float& o0, float& o1) {
    float m   = fmaxf(l0, l1);
    float t   = ex2(-fabsf(l0 - l1) * L2E);
    float lse = fmaf(lg2(1.0f + t), LN2, m);
    o0 = l0 - lse;
    o1 = l1 - lse;
}

// one 9x9 mid layer + scale-domain ELU, in -> out  (R2 champion structure)
__device__ __forceinline__ void mid_layer(const u64* __restrict__ wl,
                                          const u64* __restrict__ bl,
                                          u64 (&in)[NP][9], u64 (&out)[NP][9])
{
    // bias row: 4x LDS.128 + 1x LDS.64
    ulonglong2 b01 = *reinterpret_cast<const ulonglong2*>(bl + 0);
    ulonglong2 b23 = *reinterpret_cast<const ulonglong2*>(bl + 2);
    ulonglong2 b45 = *reinterpret_cast<const ulonglong2*>(bl + 4);
    ulonglong2 b67 = *reinterpret_cast<const ulonglong2*>(bl + 6);
    u64 b8 = bl[8];
    u64 bias[9] = {b01.x, b01.y, b23.x, b23.y, b45.x, b45.y, b67.x, b67.y, b8};

#pragma unroll
    for (int j = 0; j < 9; j++) {
        const u64* wr = wl + j * 10;
        ulonglong2 w01 = *reinterpret_cast<const ulonglong2*>(wr + 0);
        ulonglong2 w23 = *reinterpret_cast<const ulonglong2*>(wr + 2);
        ulonglong2 w45 = *reinterpret_cast<const ulonglong2*>(wr + 4);
        ulonglong2 w67 = *reinterpret_cast<const ulonglong2*>(wr + 6);
        u64 w8 = wr[8];
        u64 w[9] = {w01.x, w01.y, w23.x, w23.y, w45.x, w45.y, w67.x, w67.y, w8};

        u64 acc[NP];
#pragma unroll
        for (int p = 0; p < NP; p++) acc[p] = bias[j];
#pragma unroll
        for (int k = 0; k < 9; k++) {
#pragma unroll
            for (int p = 0; p < NP; p++) acc[p] = ffma2(w[k], in[p][k], acc[p]);
        }
#pragma unroll
        for (int p = 0; p < NP; p++) out[p][j] = elu2s(acc[p]);
    }
}

__global__ void __launch_bounds__(THREADS)
mlp_kernel(const float* __restrict__ x,
           const float* __restrict__ W1,  const float* __restrict__ b1,
           const float* __restrict__ Wm,  const float* __restrict__ bm,
           const float* __restrict__ W21, const float* __restrict__ b21,
           float* __restrict__ out)
{
    __shared__ __align__(16) u64 sw[SW_TOT];
    const int t = threadIdx.x;

    // Stage weights into shared, duplicated into both f32x2 halves, scaled per plan.
    for (int i = t; i < 19 * 81; i += THREADS) {
        int l = i / 81, r = i % 81;
        int j = r / 9,  k = r % 9;
        float v = Wm[i];
        sw[OFF_MW + l * 90 + j * 10 + k] = pk2(v, v);   // mid W unscaled
    }
    for (int i = t; i < 19 * 9; i += THREADS) {
        int l = i / 9, j = i % 9;
        float v = bm[i] * L2E;
        sw[OFF_MB + l * 10 + j] = pk2(v, v);
    }
    for (int i = t; i < 18; i += THREADS) { float v = W1[i] * L2E;   sw[OFF_W1 + i]  = pk2(v, v); }
    for (int i = t; i < 9;  i += THREADS) { float v = b1[i] * L2E;   sw[OFF_B1 + i]  = pk2(v, v); }
    for (int i = t; i < 18; i += THREADS) { float v = W21[i] * IL2E; sw[OFF_W21 + i] = pk2(v, v); }
    for (int i = t; i < 2;  i += THREADS) { float v = b21[i];        sw[OFF_B21 + i] = pk2(v, v); }
    __syncthreads();

    const int gtid = blockIdx.x * THREADS + t;

    float4 xin[NP];
    int    pidx[NP];
#pragma unroll
    for (int p = 0; p < NP; p++) {
        pidx[p] = gtid + p * TOT_THREADS;
        xin[p]  = reinterpret_cast<const float4*>(x)[pidx[p]];
    }

    u64 h[NP][9], g[NP][9];

    // ---- fc1 (pre-scaled by L2E) + ELU ----
#pragma unroll
    for (int p = 0; p < NP; p++) {
        u64 x0 = pk2(xin[p].x, xin[p].z);
        u64 x1 = pk2(xin[p].y, xin[p].w);
#pragma unroll
        for (int j = 0; j < 9; j++) {
            u64 acc = ffma2(sw[OFF_W1 + j * 2 + 0], x0, sw[OFF_B1 + j]);
            acc     = ffma2(sw[OFF_W1 + j * 2 + 1], x1, acc);
            h[p][j] = elu2s(acc);
        }
    }

    // ---- 19 mid layers: 9 x (h->g, g->h) + final h->g ----
#pragma unroll 1
    for (int l = 0; l < 9; l++) {
        mid_layer(&sw[OFF_MW + (2 * l)     * 90], &sw[OFF_MB + (2 * l)     * 10], h, g);
        mid_layer(&sw[OFF_MW + (2 * l + 1) * 90], &sw[OFF_MB + (2 * l + 1) * 10], g, h);
    }
    mid_layer(&sw[OFF_MW + 18 * 90], &sw[OFF_MB + 18 * 10], h, g);

    // ---- output layer (W21 pre-scaled 1/L2E) + log_softmax ----
#pragma unroll
    for (int p = 0; p < NP; p++) {
        u64 a0 = sw[OFF_B21 + 0];
        u64 a1 = sw[OFF_B21 + 1];
#pragma unroll
        for (int k = 0; k < 9; k++) {
            a0 = ffma2(sw[OFF_W21 + k],     g[p][k], a0);
            a1 = ffma2(sw[OFF_W21 + 9 + k], g[p][k], a1);
        }
        float l0A, l0B, l1A, l1B;
        upk2(l0A, l0B, a0);   // logit0: row A (lo), row B (hi)
        upk2(l1A, l1B, a1);

        float4 o;
        lsm2(l0A, l1A, o.x, o.y);   // row A: out[2p][0], out[2p][1]
        lsm2(l0B, l1B, o.z, o.w);   // row B
        reinterpret_cast<float4*>(out)[pidx[p]] = o;
    }
}

extern "C" void kernel_launch(void* const* d_in, const int* in_sizes, int n_in,
                              void* d_out, int out_size)
{
    const float* x   = (const float*)d_in[0];
    const float* W1  = (const float*)d_in[1];
    const float* b1  = (const float*)d_in[2];
    const float* Wm  = (const float*)d_in[3];
    const float* bm  = (const float*)d_in[4];
    const float* W21 = (const float*)d_in[5];
    const float* b21 = (const float*)d_in[6];
    float*       out = (float*)d_out;

    mlp_kernel<<<NBLOCK, THREADS>>>(x, W1, b1, Wm, bm, W21, b21, out);
}